// round 13
// baseline (speedup 1.0000x reference)
#include <cuda_runtime.h>
#include <math.h>
#include <stdio.h>

// Problem constants (confirmed)
#define NLON  720
#define MMAXC 361
#define LMAXC 360
#define NLATC 361
#define BCC   256
#define ROWS1 (BCC * NLATC)    // 92416
#define RL2   (BCC * LMAXC)    // 92160
#define BK    8
#define PADW  136              // 128 + 8 pad; 136*4B = 544 = 34*16 (float4-safe)

// Scratch
__device__ float g_fc[NLATC * MMAXC];            // [n][m] cos * 2pi/720
__device__ float g_sre[(size_t)MMAXC * ROWS1];   // [m][row], row = r*361+k
__device__ float g_o2[(size_t)MMAXC * RL2];      // [m][r][l]

// ---- f32x2 packed helpers -----------------------------------------------
__device__ __forceinline__ unsigned long long pk2(float lo, float hi) {
    unsigned long long r;
    asm("mov.b64 %0, {%1, %2};" : "=l"(r) : "f"(lo), "f"(hi));
    return r;
}
__device__ __forceinline__ void fma2(unsigned long long& d,
                                     unsigned long long a,
                                     unsigned long long b) {
    asm("fma.rn.f32x2 %0, %1, %2, %0;" : "+l"(d) : "l"(a), "l"(b));
}
__device__ __forceinline__ float2 upk2(unsigned long long v) {
    float2 r;
    asm("mov.b64 {%0, %1}, %2;" : "=f"(r.x), "=f"(r.y) : "l"(v));
    return r;
}

// -------------------------------------------------------------------------
__global__ void fmat_kernel() {
    const float scale = 0.008726646259971648f;  // 2*pi/720
    int idx = blockIdx.x * blockDim.x + threadIdx.x;
    if (idx < NLATC * MMAXC) {
        int n = idx / MMAXC, m = idx % MMAXC;
        int ph = (n * m) % NLON;
        g_fc[idx] = scale * cosf(scale * (float)ph);
    }
}

// -------------------------------------------------------------------------
// Stage 1: folded cosine DFT as GEMM (BM=128, BN=128, BK=8, double-buffered,
// f32x2 accumulation).  C[row][m] = sum_n s[n]*fc[n][m] -> g_sre[m][row]
// -------------------------------------------------------------------------
__global__ __launch_bounds__(256) void s1_gemm(const float* __restrict__ x)
{
    __shared__ __align__(16) float As[2][BK][PADW];
    __shared__ __align__(16) float Bs[2][BK][PADW];

    const int tid = threadIdx.x;
    const int tx = tid & 15, ty = tid >> 4;
    const int row0 = blockIdx.y * 128;
    const int m0   = blockIdx.x * 128;

    const int lka = tid & 7;     // A-load k
    const int lra = tid >> 3;    // A-load row base (0..31)
    const int lkb = tid >> 5;    // B-load k (0..7)
    const int lmb = tid & 31;    // B-load m base

    unsigned long long acc[4][8];
#pragma unroll
    for (int i = 0; i < 4; i++)
#pragma unroll
        for (int j = 0; j < 8; j++) acc[i][j] = 0ull;

    float ra[4], rb[4];
    const int nk = (NLATC + BK - 1) / BK;   // 46

    // prologue load (k0 = 0)
#pragma unroll
    for (int p = 0; p < 4; p++) {
        int kg = lka;
        const float* xr = x + (size_t)(row0 + lra + (p << 5)) * NLON;
        float v = xr[kg];
        if (kg >= 1) v += xr[NLON - kg];
        ra[p] = v;
    }
#pragma unroll
    for (int q = 0; q < 4; q++) {
        int mg = m0 + lmb + (q << 5);
        rb[q] = (mg < MMAXC) ? g_fc[lkb * MMAXC + mg] : 0.0f;
    }
#pragma unroll
    for (int p = 0; p < 4; p++) As[0][lka][lra + (p << 5)] = ra[p];
#pragma unroll
    for (int q = 0; q < 4; q++) Bs[0][lkb][lmb + (q << 5)] = rb[q];
    __syncthreads();

    int cur = 0;
    for (int t = 1; t <= nk; t++) {
        if (t < nk) {
            const int k0 = t * BK;
#pragma unroll
            for (int p = 0; p < 4; p++) {
                int kg = k0 + lka;
                const float* xr = x + (size_t)(row0 + lra + (p << 5)) * NLON;
                float v = 0.0f;
                if (kg < NLATC) {
                    v = xr[kg];
                    if (kg <= 359) v += xr[NLON - kg];
                }
                ra[p] = v;
            }
#pragma unroll
            for (int q = 0; q < 4; q++) {
                int kg = k0 + lkb;
                int mg = m0 + lmb + (q << 5);
                rb[q] = (kg < NLATC && mg < MMAXC) ? g_fc[kg * MMAXC + mg] : 0.0f;
            }
        }

#pragma unroll
        for (int kk = 0; kk < BK; kk++) {
            const float4 a0 = *(const float4*)&As[cur][kk][tx << 2];
            const float4 a1 = *(const float4*)&As[cur][kk][64 + (tx << 2)];
            const float4 b0 = *(const float4*)&Bs[cur][kk][ty << 2];
            const float4 b1 = *(const float4*)&Bs[cur][kk][64 + (ty << 2)];
            unsigned long long ap[4] = { pk2(a0.x, a0.y), pk2(a0.z, a0.w),
                                         pk2(a1.x, a1.y), pk2(a1.z, a1.w) };
            float bv[8] = { b0.x, b0.y, b0.z, b0.w, b1.x, b1.y, b1.z, b1.w };
#pragma unroll
            for (int j = 0; j < 8; j++) {
                unsigned long long bp = pk2(bv[j], bv[j]);
#pragma unroll
                for (int i = 0; i < 4; i++) fma2(acc[i][j], ap[i], bp);
            }
        }

        if (t < nk) {
            const int b = cur ^ 1;
#pragma unroll
            for (int p = 0; p < 4; p++) As[b][lka][lra + (p << 5)] = ra[p];
#pragma unroll
            for (int q = 0; q < 4; q++) Bs[b][lkb][lmb + (q << 5)] = rb[q];
        }
        __syncthreads();
        cur ^= 1;
    }

    // epilogue: per m-column, two float4 row-stores into g_sre[m][row]
#pragma unroll
    for (int j = 0; j < 8; j++) {
        int mg = m0 + ((j < 4) ? (ty << 2) + j : 64 + (ty << 2) + (j - 4));
        if (mg < MMAXC) {
            float* op = g_sre + (size_t)mg * ROWS1 + row0;
            float2 p0 = upk2(acc[0][j]), p1 = upk2(acc[1][j]);
            float2 p2 = upk2(acc[2][j]), p3 = upk2(acc[3][j]);
            *(float4*)&op[tx << 2]        = make_float4(p0.x, p0.y, p1.x, p1.y);
            *(float4*)&op[64 + (tx << 2)] = make_float4(p2.x, p2.y, p3.x, p3.y);
        }
    }
}

// -------------------------------------------------------------------------
// Stage 2: per-m GEMM (real part), BM=128(r), BN=128(l), BK=8, f32x2.
// A[r][k] = g_sre[m][r*361+k]; B[l][k] = W[m][l][k]; out -> g_o2[m][r][l].
// -------------------------------------------------------------------------
__global__ __launch_bounds__(256) void s2_gemm(const float* __restrict__ W)
{
    __shared__ __align__(16) float As[2][BK][PADW];
    __shared__ __align__(16) float Bs[2][BK][PADW];

    const int tid = threadIdx.x;
    const int tx = tid & 15, ty = tid >> 4;
    const int m  = blockIdx.z;
    const int r0 = blockIdx.y * 128;
    const int l0 = blockIdx.x * 128;

    const float* __restrict__ Am = g_sre + (size_t)m * ROWS1;
    const float* __restrict__ Bw = W + (size_t)m * LMAXC * NLATC;

    const int lk = tid & 7;      // k-sub for both loads
    const int lr = tid >> 3;     // row/l base (0..31)

    unsigned long long acc[4][8];
#pragma unroll
    for (int i = 0; i < 4; i++)
#pragma unroll
        for (int j = 0; j < 8; j++) acc[i][j] = 0ull;

    float ra[4], rb[4];
    const int nk = (NLATC + BK - 1) / BK;   // 46

    // prologue (k0 = 0)
#pragma unroll
    for (int p = 0; p < 4; p++) {
        int r = r0 + lr + (p << 5);
        ra[p] = Am[(size_t)r * NLATC + lk];
        int lg = l0 + lr + (p << 5);
        rb[p] = (lg < LMAXC) ? Bw[(size_t)lg * NLATC + lk] : 0.0f;
    }
#pragma unroll
    for (int p = 0; p < 4; p++) {
        As[0][lk][lr + (p << 5)] = ra[p];
        Bs[0][lk][lr + (p << 5)] = rb[p];
    }
    __syncthreads();

    int cur = 0;
    for (int t = 1; t <= nk; t++) {
        if (t < nk) {
            const int k0 = t * BK;
            const int kg = k0 + lk;
            const bool kok = (kg < NLATC);
#pragma unroll
            for (int p = 0; p < 4; p++) {
                int r = r0 + lr + (p << 5);
                ra[p] = kok ? Am[(size_t)r * NLATC + kg] : 0.0f;
                int lg = l0 + lr + (p << 5);
                rb[p] = (kok && lg < LMAXC) ? Bw[(size_t)lg * NLATC + kg] : 0.0f;
            }
        }

#pragma unroll
        for (int kk = 0; kk < BK; kk++) {
            const float4 a0 = *(const float4*)&As[cur][kk][tx << 2];
            const float4 a1 = *(const float4*)&As[cur][kk][64 + (tx << 2)];
            const float4 b0 = *(const float4*)&Bs[cur][kk][ty << 2];
            const float4 b1 = *(const float4*)&Bs[cur][kk][64 + (ty << 2)];
            unsigned long long ap[4] = { pk2(a0.x, a0.y), pk2(a0.z, a0.w),
                                         pk2(a1.x, a1.y), pk2(a1.z, a1.w) };
            float bv[8] = { b0.x, b0.y, b0.z, b0.w, b1.x, b1.y, b1.z, b1.w };
#pragma unroll
            for (int j = 0; j < 8; j++) {
                unsigned long long bp = pk2(bv[j], bv[j]);
#pragma unroll
                for (int i = 0; i < 4; i++) fma2(acc[i][j], ap[i], bp);
            }
        }

        if (t < nk) {
            const int b = cur ^ 1;
#pragma unroll
            for (int p = 0; p < 4; p++) {
                As[b][lk][lr + (p << 5)] = ra[p];
                Bs[b][lk][lr + (p << 5)] = rb[p];
            }
        }
        __syncthreads();
        cur ^= 1;
    }

    // epilogue: per row, two float4 l-contiguous stores into g_o2[m][r][l]
#pragma unroll
    for (int lrow = 0; lrow < 8; lrow++) {
        int r = r0 + ((lrow < 4) ? (tx << 2) + lrow : 64 + (tx << 2) + (lrow - 4));
        float v[8];
#pragma unroll
        for (int j = 0; j < 8; j++) {
            float2 t2 = upk2(acc[lrow >> 1][j]);
            v[j] = (lrow & 1) ? t2.y : t2.x;
        }
        float* op = g_o2 + ((size_t)m * BCC + r) * LMAXC + l0;
        if (l0 + (ty << 2) + 3 < LMAXC)
            *(float4*)&op[ty << 2] = make_float4(v[0], v[1], v[2], v[3]);
        if (l0 + 64 + (ty << 2) + 3 < LMAXC)
            *(float4*)&op[64 + (ty << 2)] = make_float4(v[4], v[5], v[6], v[7]);
    }
}

// -------------------------------------------------------------------------
// Transpose: g_o2[m][rl] (rl = r*360+l, 92160) -> out[rl*361 + m], both
// sides coalesced via 32x32 smem tile.
// -------------------------------------------------------------------------
__global__ __launch_bounds__(256) void tr_kernel(float* __restrict__ out,
                                                 size_t out_n)
{
    __shared__ float t[32][33];
    const int rl0 = blockIdx.x * 32;
    const int m0  = blockIdx.y * 32;

#pragma unroll
    for (int q = 0; q < 4; q++) {
        int mm = m0 + threadIdx.y + (q << 3);
        t[threadIdx.y + (q << 3)][threadIdx.x] =
            (mm < MMAXC) ? g_o2[(size_t)mm * RL2 + rl0 + threadIdx.x] : 0.0f;
    }
    __syncthreads();
#pragma unroll
    for (int q = 0; q < 4; q++) {
        int rl = rl0 + threadIdx.y + (q << 3);
        int mm = m0 + threadIdx.x;
        if (mm < MMAXC) {
            size_t idx = (size_t)rl * MMAXC + mm;
            if (idx < out_n) out[idx] = t[threadIdx.x][threadIdx.y + (q << 3)];
        }
    }
}

// -------------------------------------------------------------------------
extern "C" void kernel_launch(void* const* d_in, const int* in_sizes, int n_in,
                              void* d_out, int out_size)
{
    cudaStreamCaptureStatus cs = cudaStreamCaptureStatusNone;
    cudaStreamIsCapturing(0, &cs);
    const int live = (cs == cudaStreamCaptureStatusNone);

#define CHK(tag) do { if (live) { \
    cudaError_t _e = cudaDeviceSynchronize(); \
    fprintf(stderr, "[diag] %-6s: %s\n", tag, cudaGetErrorName(_e)); } } while (0)

    int xi = 0, wi = (n_in >= 2) ? 1 : 0;
    if (n_in >= 2 && in_sizes[1] > in_sizes[0]) { xi = 1; wi = 0; }
    const float* x = (const float*)d_in[xi];
    const float* w = (const float*)d_in[wi];
    float* out = (float*)d_out;
    size_t out_n = (size_t)(long long)out_size;

    fmat_kernel<<<(NLATC * MMAXC + 255) / 256, 256>>>();
    CHK("fmat");

    dim3 g1(3, 722);
    s1_gemm<<<g1, 256>>>(x);
    CHK("s1");

    dim3 g2(3, 2, 361);
    s2_gemm<<<g2, 256>>>(w);
    CHK("s2");

    dim3 g3(RL2 / 32, (MMAXC + 31) / 32);
    tr_kernel<<<g3, dim3(32, 8)>>>(out, out_n);
    CHK("tr");
#undef CHK
}

// round 14
// speedup vs baseline: 1.4874x; 1.4874x over previous
#include <cuda_runtime.h>
#include <math.h>
#include <stdio.h>

// Problem constants (confirmed)
#define NLON  720
#define MMAXC 361
#define LMAXC 360
#define NLATC 361
#define BCC   256
#define ROWS1 (BCC * NLATC)    // 92416
#define RL2   (BCC * LMAXC)    // 92160
#define BK    8
#define PADW  136              // 128 + 8 pad; 136*4B = 544 = 34*16 (float4-safe)

// Scratch
__device__ float g_fc[NLATC * MMAXC];            // [n][m] cos * 2pi/720
__device__ float g_sre[(size_t)MMAXC * ROWS1];   // [m][row], row = r*361+k
__device__ float g_o2[(size_t)MMAXC * RL2];      // [m][r][l]

// ---- f32x2 packed helpers -----------------------------------------------
__device__ __forceinline__ unsigned long long pk2(float lo, float hi) {
    unsigned long long r;
    asm("mov.b64 %0, {%1, %2};" : "=l"(r) : "f"(lo), "f"(hi));
    return r;
}
__device__ __forceinline__ void fma2(unsigned long long& d,
                                     unsigned long long a,
                                     unsigned long long b) {
    asm("fma.rn.f32x2 %0, %1, %2, %0;" : "+l"(d) : "l"(a), "l"(b));
}
__device__ __forceinline__ float2 upk2(unsigned long long v) {
    float2 r;
    asm("mov.b64 {%0, %1}, %2;" : "=f"(r.x), "=f"(r.y) : "l"(v));
    return r;
}

// -------------------------------------------------------------------------
__global__ void fmat_kernel() {
    const float scale = 0.008726646259971648f;  // 2*pi/720
    int idx = blockIdx.x * blockDim.x + threadIdx.x;
    if (idx < NLATC * MMAXC) {
        int n = idx / MMAXC, m = idx % MMAXC;
        int ph = (n * m) % NLON;
        g_fc[idx] = scale * cosf(scale * (float)ph);
    }
}

// -------------------------------------------------------------------------
// Stage 1: folded cosine DFT as GEMM (BM=128, BN=128, BK=8, double-buffered,
// f32x2 accumulation).  C[row][m] = sum_n s[n]*fc[n][m] -> g_sre[m][row]
// -------------------------------------------------------------------------
__global__ __launch_bounds__(256) void s1_gemm(const float* __restrict__ x)
{
    __shared__ __align__(16) float As[2][BK][PADW];
    __shared__ __align__(16) float Bs[2][BK][PADW];

    const int tid = threadIdx.x;
    const int tx = tid & 15, ty = tid >> 4;
    const int row0 = blockIdx.y * 128;
    const int m0   = blockIdx.x * 128;

    const int lka = tid & 7;     // A-load k
    const int lra = tid >> 3;    // A-load row base (0..31)
    const int lkb = tid >> 5;    // B-load k (0..7)
    const int lmb = tid & 31;    // B-load m base

    unsigned long long acc[4][8];
#pragma unroll
    for (int i = 0; i < 4; i++)
#pragma unroll
        for (int j = 0; j < 8; j++) acc[i][j] = 0ull;

    float ra[4], rb[4];
    const int nk = (NLATC + BK - 1) / BK;   // 46

    // prologue load (k0 = 0)
#pragma unroll
    for (int p = 0; p < 4; p++) {
        int kg = lka;
        const float* xr = x + (size_t)(row0 + lra + (p << 5)) * NLON;
        float v = xr[kg];
        if (kg >= 1) v += xr[NLON - kg];
        ra[p] = v;
    }
#pragma unroll
    for (int q = 0; q < 4; q++) {
        int mg = m0 + lmb + (q << 5);
        rb[q] = (mg < MMAXC) ? g_fc[lkb * MMAXC + mg] : 0.0f;
    }
#pragma unroll
    for (int p = 0; p < 4; p++) As[0][lka][lra + (p << 5)] = ra[p];
#pragma unroll
    for (int q = 0; q < 4; q++) Bs[0][lkb][lmb + (q << 5)] = rb[q];
    __syncthreads();

    int cur = 0;
    for (int t = 1; t <= nk; t++) {
        if (t < nk) {
            const int k0 = t * BK;
#pragma unroll
            for (int p = 0; p < 4; p++) {
                int kg = k0 + lka;
                const float* xr = x + (size_t)(row0 + lra + (p << 5)) * NLON;
                float v = 0.0f;
                if (kg < NLATC) {
                    v = xr[kg];
                    if (kg <= 359) v += xr[NLON - kg];
                }
                ra[p] = v;
            }
#pragma unroll
            for (int q = 0; q < 4; q++) {
                int kg = k0 + lkb;
                int mg = m0 + lmb + (q << 5);
                rb[q] = (kg < NLATC && mg < MMAXC) ? g_fc[kg * MMAXC + mg] : 0.0f;
            }
        }

#pragma unroll
        for (int kk = 0; kk < BK; kk++) {
            const float4 a0 = *(const float4*)&As[cur][kk][tx << 2];
            const float4 a1 = *(const float4*)&As[cur][kk][64 + (tx << 2)];
            const float4 b0 = *(const float4*)&Bs[cur][kk][ty << 2];
            const float4 b1 = *(const float4*)&Bs[cur][kk][64 + (ty << 2)];
            unsigned long long ap[4] = { pk2(a0.x, a0.y), pk2(a0.z, a0.w),
                                         pk2(a1.x, a1.y), pk2(a1.z, a1.w) };
            float bv[8] = { b0.x, b0.y, b0.z, b0.w, b1.x, b1.y, b1.z, b1.w };
#pragma unroll
            for (int j = 0; j < 8; j++) {
                unsigned long long bp = pk2(bv[j], bv[j]);
#pragma unroll
                for (int i = 0; i < 4; i++) fma2(acc[i][j], ap[i], bp);
            }
        }

        if (t < nk) {
            const int b = cur ^ 1;
#pragma unroll
            for (int p = 0; p < 4; p++) As[b][lka][lra + (p << 5)] = ra[p];
#pragma unroll
            for (int q = 0; q < 4; q++) Bs[b][lkb][lmb + (q << 5)] = rb[q];
        }
        __syncthreads();
        cur ^= 1;
    }

    // epilogue: per m-column, two float4 row-stores into g_sre[m][row]
#pragma unroll
    for (int j = 0; j < 8; j++) {
        int mg = m0 + ((j < 4) ? (ty << 2) + j : 64 + (ty << 2) + (j - 4));
        if (mg < MMAXC) {
            float* op = g_sre + (size_t)mg * ROWS1 + row0;
            float2 p0 = upk2(acc[0][j]), p1 = upk2(acc[1][j]);
            float2 p2 = upk2(acc[2][j]), p3 = upk2(acc[3][j]);
            *(float4*)&op[tx << 2]        = make_float4(p0.x, p0.y, p1.x, p1.y);
            *(float4*)&op[64 + (tx << 2)] = make_float4(p2.x, p2.y, p3.x, p3.y);
        }
    }
}

// -------------------------------------------------------------------------
// Stage 2: per-m GEMM (real part), BM=128(r), BN=128(l), BK=8, f32x2.
// A[r][k] = g_sre[m][r*361+k]; B[l][k] = W[m][l][k]; out -> g_o2[m][r][l].
// -------------------------------------------------------------------------
__global__ __launch_bounds__(256) void s2_gemm(const float* __restrict__ W)
{
    __shared__ __align__(16) float As[2][BK][PADW];
    __shared__ __align__(16) float Bs[2][BK][PADW];

    const int tid = threadIdx.x;
    const int tx = tid & 15, ty = tid >> 4;
    const int m  = blockIdx.z;
    const int r0 = blockIdx.y * 128;
    const int l0 = blockIdx.x * 128;

    const float* __restrict__ Am = g_sre + (size_t)m * ROWS1;
    const float* __restrict__ Bw = W + (size_t)m * LMAXC * NLATC;

    const int lk = tid & 7;      // k-sub for both loads
    const int lr = tid >> 3;     // row/l base (0..31)

    unsigned long long acc[4][8];
#pragma unroll
    for (int i = 0; i < 4; i++)
#pragma unroll
        for (int j = 0; j < 8; j++) acc[i][j] = 0ull;

    float ra[4], rb[4];
    const int nk = (NLATC + BK - 1) / BK;   // 46

    // prologue (k0 = 0)
#pragma unroll
    for (int p = 0; p < 4; p++) {
        int r = r0 + lr + (p << 5);
        ra[p] = Am[(size_t)r * NLATC + lk];
        int lg = l0 + lr + (p << 5);
        rb[p] = (lg < LMAXC) ? Bw[(size_t)lg * NLATC + lk] : 0.0f;
    }
#pragma unroll
    for (int p = 0; p < 4; p++) {
        As[0][lk][lr + (p << 5)] = ra[p];
        Bs[0][lk][lr + (p << 5)] = rb[p];
    }
    __syncthreads();

    int cur = 0;
    for (int t = 1; t <= nk; t++) {
        if (t < nk) {
            const int k0 = t * BK;
            const int kg = k0 + lk;
            const bool kok = (kg < NLATC);
#pragma unroll
            for (int p = 0; p < 4; p++) {
                int r = r0 + lr + (p << 5);
                ra[p] = kok ? Am[(size_t)r * NLATC + kg] : 0.0f;
                int lg = l0 + lr + (p << 5);
                rb[p] = (kok && lg < LMAXC) ? Bw[(size_t)lg * NLATC + kg] : 0.0f;
            }
        }

#pragma unroll
        for (int kk = 0; kk < BK; kk++) {
            const float4 a0 = *(const float4*)&As[cur][kk][tx << 2];
            const float4 a1 = *(const float4*)&As[cur][kk][64 + (tx << 2)];
            const float4 b0 = *(const float4*)&Bs[cur][kk][ty << 2];
            const float4 b1 = *(const float4*)&Bs[cur][kk][64 + (ty << 2)];
            unsigned long long ap[4] = { pk2(a0.x, a0.y), pk2(a0.z, a0.w),
                                         pk2(a1.x, a1.y), pk2(a1.z, a1.w) };
            float bv[8] = { b0.x, b0.y, b0.z, b0.w, b1.x, b1.y, b1.z, b1.w };
#pragma unroll
            for (int j = 0; j < 8; j++) {
                unsigned long long bp = pk2(bv[j], bv[j]);
#pragma unroll
                for (int i = 0; i < 4; i++) fma2(acc[i][j], ap[i], bp);
            }
        }

        if (t < nk) {
            const int b = cur ^ 1;
#pragma unroll
            for (int p = 0; p < 4; p++) {
                As[b][lk][lr + (p << 5)] = ra[p];
                Bs[b][lk][lr + (p << 5)] = rb[p];
            }
        }
        __syncthreads();
        cur ^= 1;
    }

    // epilogue: per row, two float4 l-contiguous stores into g_o2[m][r][l]
#pragma unroll
    for (int lrow = 0; lrow < 8; lrow++) {
        int r = r0 + ((lrow < 4) ? (tx << 2) + lrow : 64 + (tx << 2) + (lrow - 4));
        float v[8];
#pragma unroll
        for (int j = 0; j < 8; j++) {
            float2 t2 = upk2(acc[lrow >> 1][j]);
            v[j] = (lrow & 1) ? t2.y : t2.x;
        }
        float* op = g_o2 + ((size_t)m * BCC + r) * LMAXC + l0;
        if (l0 + (ty << 2) + 3 < LMAXC)
            *(float4*)&op[ty << 2] = make_float4(v[0], v[1], v[2], v[3]);
        if (l0 + 64 + (ty << 2) + 3 < LMAXC)
            *(float4*)&op[64 + (ty << 2)] = make_float4(v[4], v[5], v[6], v[7]);
    }
}

// -------------------------------------------------------------------------
// Transpose: g_o2[m][rl] (rl = r*360+l, 92160) -> out[rl*361 + m], both
// sides coalesced via 32x32 smem tile.
// -------------------------------------------------------------------------
__global__ __launch_bounds__(256) void tr_kernel(float* __restrict__ out,
                                                 size_t out_n)
{
    __shared__ float t[32][33];
    const int rl0 = blockIdx.x * 32;
    const int m0  = blockIdx.y * 32;

#pragma unroll
    for (int q = 0; q < 4; q++) {
        int mm = m0 + threadIdx.y + (q << 3);
        t[threadIdx.y + (q << 3)][threadIdx.x] =
            (mm < MMAXC) ? g_o2[(size_t)mm * RL2 + rl0 + threadIdx.x] : 0.0f;
    }
    __syncthreads();
#pragma unroll
    for (int q = 0; q < 4; q++) {
        int rl = rl0 + threadIdx.y + (q << 3);
        int mm = m0 + threadIdx.x;
        if (mm < MMAXC) {
            size_t idx = (size_t)rl * MMAXC + mm;
            if (idx < out_n) out[idx] = t[threadIdx.x][threadIdx.y + (q << 3)];
        }
    }
}

// -------------------------------------------------------------------------
extern "C" void kernel_launch(void* const* d_in, const int* in_sizes, int n_in,
                              void* d_out, int out_size)
{
    cudaStreamCaptureStatus cs = cudaStreamCaptureStatusNone;
    cudaStreamIsCapturing(0, &cs);
    const int live = (cs == cudaStreamCaptureStatusNone);

#define CHK(tag) do { if (live) { \
    cudaError_t _e = cudaDeviceSynchronize(); \
    fprintf(stderr, "[diag] %-6s: %s\n", tag, cudaGetErrorName(_e)); } } while (0)

    int xi = 0, wi = (n_in >= 2) ? 1 : 0;
    if (n_in >= 2 && in_sizes[1] > in_sizes[0]) { xi = 1; wi = 0; }
    const float* x = (const float*)d_in[xi];
    const float* w = (const float*)d_in[wi];
    float* out = (float*)d_out;
    size_t out_n = (size_t)(long long)out_size;

    fmat_kernel<<<(NLATC * MMAXC + 255) / 256, 256>>>();
    CHK("fmat");

    dim3 g1(3, 722);
    s1_gemm<<<g1, 256>>>(x);
    CHK("s1");

    dim3 g2(3, 2, 361);
    s2_gemm<<<g2, 256>>>(w);
    CHK("s2");

    dim3 g3(RL2 / 32, (MMAXC + 31) / 32);
    tr_kernel<<<g3, dim3(32, 8)>>>(out, out_n);
    CHK("tr");
#undef CHK
}

// round 15
// speedup vs baseline: 1.4891x; 1.0012x over previous
#include <cuda_runtime.h>
#include <math.h>
#include <stdio.h>

// Problem constants (confirmed)
#define NLON  720
#define MMAXC 361
#define LMAXC 360
#define NLATC 361
#define BCC   256
#define ROWS1 (BCC * NLATC)    // 92416
#define RL2   (BCC * LMAXC)    // 92160
#define BK    8
#define PADW  136              // 128 + 8 pad; 136*4B = 544 = 34*16 (float4-safe)

// Scratch
__device__ float g_fc[NLATC * MMAXC];            // [n][m] cos * 2pi/720
__device__ float g_sre[(size_t)MMAXC * ROWS1];   // [m][row], row = r*361+k
__device__ float g_o2[(size_t)MMAXC * RL2];      // [m][r][l]

// ---- f32x2 packed helpers -----------------------------------------------
__device__ __forceinline__ unsigned long long pk2(float lo, float hi) {
    unsigned long long r;
    asm("mov.b64 %0, {%1, %2};" : "=l"(r) : "f"(lo), "f"(hi));
    return r;
}
__device__ __forceinline__ void fma2(unsigned long long& d,
                                     unsigned long long a,
                                     unsigned long long b) {
    asm("fma.rn.f32x2 %0, %1, %2, %0;" : "+l"(d) : "l"(a), "l"(b));
}
__device__ __forceinline__ float2 upk2(unsigned long long v) {
    float2 r;
    asm("mov.b64 {%0, %1}, %2;" : "=f"(r.x), "=f"(r.y) : "l"(v));
    return r;
}

// -------------------------------------------------------------------------
__global__ void fmat_kernel() {
    const float scale = 0.008726646259971648f;  // 2*pi/720
    int idx = blockIdx.x * blockDim.x + threadIdx.x;
    if (idx < NLATC * MMAXC) {
        int n = idx / MMAXC, m = idx % MMAXC;
        int ph = (n * m) % NLON;
        g_fc[idx] = scale * cosf(scale * (float)ph);
    }
}

// -------------------------------------------------------------------------
// Stage 1: folded cosine DFT as GEMM (BM=128, BN=128, BK=8, double-buffered,
// f32x2 accumulation).  C[row][m] = sum_n s[n]*fc[n][m] -> g_sre[m][row]
// -------------------------------------------------------------------------
__global__ __launch_bounds__(256) void s1_gemm(const float* __restrict__ x)
{
    __shared__ __align__(16) float As[2][BK][PADW];
    __shared__ __align__(16) float Bs[2][BK][PADW];

    const int tid = threadIdx.x;
    const int tx = tid & 15, ty = tid >> 4;
    const int row0 = blockIdx.y * 128;
    const int m0   = blockIdx.x * 128;

    const int lka = tid & 7;     // A-load k
    const int lra = tid >> 3;    // A-load row base (0..31)
    const int lkb = tid >> 5;    // B-load k (0..7)
    const int lmb = tid & 31;    // B-load m base

    unsigned long long acc[4][8];
#pragma unroll
    for (int i = 0; i < 4; i++)
#pragma unroll
        for (int j = 0; j < 8; j++) acc[i][j] = 0ull;

    float ra[4], rb[4];
    const int nk = (NLATC + BK - 1) / BK;   // 46

    // prologue load (k0 = 0)
#pragma unroll
    for (int p = 0; p < 4; p++) {
        int kg = lka;
        const float* xr = x + (size_t)(row0 + lra + (p << 5)) * NLON;
        float v = xr[kg];
        if (kg >= 1) v += xr[NLON - kg];
        ra[p] = v;
    }
#pragma unroll
    for (int q = 0; q < 4; q++) {
        int mg = m0 + lmb + (q << 5);
        rb[q] = (mg < MMAXC) ? g_fc[lkb * MMAXC + mg] : 0.0f;
    }
#pragma unroll
    for (int p = 0; p < 4; p++) As[0][lka][lra + (p << 5)] = ra[p];
#pragma unroll
    for (int q = 0; q < 4; q++) Bs[0][lkb][lmb + (q << 5)] = rb[q];
    __syncthreads();

    int cur = 0;
    for (int t = 1; t <= nk; t++) {
        if (t < nk) {
            const int k0 = t * BK;
#pragma unroll
            for (int p = 0; p < 4; p++) {
                int kg = k0 + lka;
                const float* xr = x + (size_t)(row0 + lra + (p << 5)) * NLON;
                float v = 0.0f;
                if (kg < NLATC) {
                    v = xr[kg];
                    if (kg <= 359) v += xr[NLON - kg];
                }
                ra[p] = v;
            }
#pragma unroll
            for (int q = 0; q < 4; q++) {
                int kg = k0 + lkb;
                int mg = m0 + lmb + (q << 5);
                rb[q] = (kg < NLATC && mg < MMAXC) ? g_fc[kg * MMAXC + mg] : 0.0f;
            }
        }

#pragma unroll
        for (int kk = 0; kk < BK; kk++) {
            const float4 a0 = *(const float4*)&As[cur][kk][tx << 2];
            const float4 a1 = *(const float4*)&As[cur][kk][64 + (tx << 2)];
            const float4 b0 = *(const float4*)&Bs[cur][kk][ty << 2];
            const float4 b1 = *(const float4*)&Bs[cur][kk][64 + (ty << 2)];
            unsigned long long ap[4] = { pk2(a0.x, a0.y), pk2(a0.z, a0.w),
                                         pk2(a1.x, a1.y), pk2(a1.z, a1.w) };
            float bv[8] = { b0.x, b0.y, b0.z, b0.w, b1.x, b1.y, b1.z, b1.w };
#pragma unroll
            for (int j = 0; j < 8; j++) {
                unsigned long long bp = pk2(bv[j], bv[j]);
#pragma unroll
                for (int i = 0; i < 4; i++) fma2(acc[i][j], ap[i], bp);
            }
        }

        if (t < nk) {
            const int b = cur ^ 1;
#pragma unroll
            for (int p = 0; p < 4; p++) As[b][lka][lra + (p << 5)] = ra[p];
#pragma unroll
            for (int q = 0; q < 4; q++) Bs[b][lkb][lmb + (q << 5)] = rb[q];
        }
        __syncthreads();
        cur ^= 1;
    }

    // epilogue: per m-column, two float4 row-stores into g_sre[m][row]
#pragma unroll
    for (int j = 0; j < 8; j++) {
        int mg = m0 + ((j < 4) ? (ty << 2) + j : 64 + (ty << 2) + (j - 4));
        if (mg < MMAXC) {
            float* op = g_sre + (size_t)mg * ROWS1 + row0;
            float2 p0 = upk2(acc[0][j]), p1 = upk2(acc[1][j]);
            float2 p2 = upk2(acc[2][j]), p3 = upk2(acc[3][j]);
            *(float4*)&op[tx << 2]        = make_float4(p0.x, p0.y, p1.x, p1.y);
            *(float4*)&op[64 + (tx << 2)] = make_float4(p2.x, p2.y, p3.x, p3.y);
        }
    }
}

// -------------------------------------------------------------------------
// Stage 2: per-m GEMM (real part), BM=128(r), BN=128(l), BK=8, f32x2.
// A[r][k] = g_sre[m][r*361+k]; B[l][k] = W[m][l][k]; out -> g_o2[m][r][l].
// -------------------------------------------------------------------------
__global__ __launch_bounds__(256) void s2_gemm(const float* __restrict__ W)
{
    __shared__ __align__(16) float As[2][BK][PADW];
    __shared__ __align__(16) float Bs[2][BK][PADW];

    const int tid = threadIdx.x;
    const int tx = tid & 15, ty = tid >> 4;
    const int m  = blockIdx.z;
    const int r0 = blockIdx.y * 128;
    const int l0 = blockIdx.x * 128;

    const float* __restrict__ Am = g_sre + (size_t)m * ROWS1;
    const float* __restrict__ Bw = W + (size_t)m * LMAXC * NLATC;

    const int lk = tid & 7;      // k-sub for both loads
    const int lr = tid >> 3;     // row/l base (0..31)

    unsigned long long acc[4][8];
#pragma unroll
    for (int i = 0; i < 4; i++)
#pragma unroll
        for (int j = 0; j < 8; j++) acc[i][j] = 0ull;

    float ra[4], rb[4];
    const int nk = (NLATC + BK - 1) / BK;   // 46

    // prologue (k0 = 0)
#pragma unroll
    for (int p = 0; p < 4; p++) {
        int r = r0 + lr + (p << 5);
        ra[p] = Am[(size_t)r * NLATC + lk];
        int lg = l0 + lr + (p << 5);
        rb[p] = (lg < LMAXC) ? Bw[(size_t)lg * NLATC + lk] : 0.0f;
    }
#pragma unroll
    for (int p = 0; p < 4; p++) {
        As[0][lk][lr + (p << 5)] = ra[p];
        Bs[0][lk][lr + (p << 5)] = rb[p];
    }
    __syncthreads();

    int cur = 0;
    for (int t = 1; t <= nk; t++) {
        if (t < nk) {
            const int k0 = t * BK;
            const int kg = k0 + lk;
            const bool kok = (kg < NLATC);
#pragma unroll
            for (int p = 0; p < 4; p++) {
                int r = r0 + lr + (p << 5);
                ra[p] = kok ? Am[(size_t)r * NLATC + kg] : 0.0f;
                int lg = l0 + lr + (p << 5);
                rb[p] = (kok && lg < LMAXC) ? Bw[(size_t)lg * NLATC + kg] : 0.0f;
            }
        }

#pragma unroll
        for (int kk = 0; kk < BK; kk++) {
            const float4 a0 = *(const float4*)&As[cur][kk][tx << 2];
            const float4 a1 = *(const float4*)&As[cur][kk][64 + (tx << 2)];
            const float4 b0 = *(const float4*)&Bs[cur][kk][ty << 2];
            const float4 b1 = *(const float4*)&Bs[cur][kk][64 + (ty << 2)];
            unsigned long long ap[4] = { pk2(a0.x, a0.y), pk2(a0.z, a0.w),
                                         pk2(a1.x, a1.y), pk2(a1.z, a1.w) };
            float bv[8] = { b0.x, b0.y, b0.z, b0.w, b1.x, b1.y, b1.z, b1.w };
#pragma unroll
            for (int j = 0; j < 8; j++) {
                unsigned long long bp = pk2(bv[j], bv[j]);
#pragma unroll
                for (int i = 0; i < 4; i++) fma2(acc[i][j], ap[i], bp);
            }
        }

        if (t < nk) {
            const int b = cur ^ 1;
#pragma unroll
            for (int p = 0; p < 4; p++) {
                As[b][lk][lr + (p << 5)] = ra[p];
                Bs[b][lk][lr + (p << 5)] = rb[p];
            }
        }
        __syncthreads();
        cur ^= 1;
    }

    // epilogue: per row, two float4 l-contiguous stores into g_o2[m][r][l]
#pragma unroll
    for (int lrow = 0; lrow < 8; lrow++) {
        int r = r0 + ((lrow < 4) ? (tx << 2) + lrow : 64 + (tx << 2) + (lrow - 4));
        float v[8];
#pragma unroll
        for (int j = 0; j < 8; j++) {
            float2 t2 = upk2(acc[lrow >> 1][j]);
            v[j] = (lrow & 1) ? t2.y : t2.x;
        }
        float* op = g_o2 + ((size_t)m * BCC + r) * LMAXC + l0;
        if (l0 + (ty << 2) + 3 < LMAXC)
            *(float4*)&op[ty << 2] = make_float4(v[0], v[1], v[2], v[3]);
        if (l0 + 64 + (ty << 2) + 3 < LMAXC)
            *(float4*)&op[64 + (ty << 2)] = make_float4(v[4], v[5], v[6], v[7]);
    }
}

// -------------------------------------------------------------------------
// Transpose: g_o2[m][rl] (rl = r*360+l, 92160) -> out[rl*361 + m], both
// sides coalesced via 32x32 smem tile.
// -------------------------------------------------------------------------
__global__ __launch_bounds__(256) void tr_kernel(float* __restrict__ out,
                                                 size_t out_n)
{
    __shared__ float t[32][33];
    const int rl0 = blockIdx.x * 32;
    const int m0  = blockIdx.y * 32;

#pragma unroll
    for (int q = 0; q < 4; q++) {
        int mm = m0 + threadIdx.y + (q << 3);
        t[threadIdx.y + (q << 3)][threadIdx.x] =
            (mm < MMAXC) ? g_o2[(size_t)mm * RL2 + rl0 + threadIdx.x] : 0.0f;
    }
    __syncthreads();
#pragma unroll
    for (int q = 0; q < 4; q++) {
        int rl = rl0 + threadIdx.y + (q << 3);
        int mm = m0 + threadIdx.x;
        if (mm < MMAXC) {
            size_t idx = (size_t)rl * MMAXC + mm;
            if (idx < out_n) out[idx] = t[threadIdx.x][threadIdx.y + (q << 3)];
        }
    }
}

// -------------------------------------------------------------------------
extern "C" void kernel_launch(void* const* d_in, const int* in_sizes, int n_in,
                              void* d_out, int out_size)
{
    cudaStreamCaptureStatus cs = cudaStreamCaptureStatusNone;
    cudaStreamIsCapturing(0, &cs);
    const int live = (cs == cudaStreamCaptureStatusNone);

#define CHK(tag) do { if (live) { \
    cudaError_t _e = cudaDeviceSynchronize(); \
    fprintf(stderr, "[diag] %-6s: %s\n", tag, cudaGetErrorName(_e)); } } while (0)

    int xi = 0, wi = (n_in >= 2) ? 1 : 0;
    if (n_in >= 2 && in_sizes[1] > in_sizes[0]) { xi = 1; wi = 0; }
    const float* x = (const float*)d_in[xi];
    const float* w = (const float*)d_in[wi];
    float* out = (float*)d_out;
    size_t out_n = (size_t)(long long)out_size;

    fmat_kernel<<<(NLATC * MMAXC + 255) / 256, 256>>>();
    CHK("fmat");

    dim3 g1(3, 722);
    s1_gemm<<<g1, 256>>>(x);
    CHK("s1");

    dim3 g2(3, 2, 361);
    s2_gemm<<<g2, 256>>>(w);
    CHK("s2");

    dim3 g3(RL2 / 32, (MMAXC + 31) / 32);
    tr_kernel<<<g3, dim3(32, 8)>>>(out, out_n);
    CHK("tr");
#undef CHK
}